// round 12
// baseline (speedup 1.0000x reference)
#include <cuda_runtime.h>
#include <cstdint>

#define WSZ   7
#define SHF   3
#define NTOK  49
#define HW    112
#define NWIN  16
#define BATCH 32

// shared memory layout (32-bit word offsets). Matrix tiles hold tf32 BIT
// PATTERNS (uint32); BT holds floats.
#define XS    0        // 64 x 100 (x window, tf32 bits, rows 49-63 zero)
#define QS    6400     // 64 x 36   tf32 bits
#define KS    8704     // 64 x 36   tf32 bits
#define VS    11008    // V^T 32 x 68 tf32 bits
#define SMS   13312    // 64 x 60  probs (tf32 bits)
#define OH    13312    // 64 x 36  per-head attn out (tf32 bits), aliases SMS
#define BT    17152    // 507 bias table (float)
#define RSOFF 17664    // 64 ints (region ids)
#define SMEM_WORDS (17664 + 64)
#define SMEM_BYTES (SMEM_WORDS * 4)

__device__ uint32_t g_qkvw[96 * 288];   // tf32-bit copy of qkv_w
__device__ uint32_t g_projw[96 * 96];   // tf32-bit copy of proj_w

__device__ __forceinline__ uint32_t f2tf(float f) {
    uint32_t r;
    asm("cvt.rna.tf32.f32 %0, %1;" : "=r"(r) : "f"(f));
    return r;
}

__device__ __forceinline__ void mma8(float* c,
    uint32_t a0, uint32_t a1, uint32_t a2, uint32_t a3,
    uint32_t b0, uint32_t b1)
{
    asm volatile(
        "mma.sync.aligned.m16n8k8.row.col.f32.tf32.tf32.f32 "
        "{%0,%1,%2,%3},{%4,%5,%6,%7},{%8,%9},{%0,%1,%2,%3};\n"
        : "+f"(c[0]), "+f"(c[1]), "+f"(c[2]), "+f"(c[3])
        : "r"(a0), "r"(a1), "r"(a2), "r"(a3), "r"(b0), "r"(b1));
}

__global__ void __launch_bounds__(256) prep_kernel(
    const float* __restrict__ qkv_w, const float* __restrict__ proj_w)
{
    int i = blockIdx.x * 256 + threadIdx.x;
    if (i < 96 * 288) g_qkvw[i] = f2tf(qkv_w[i]);
    if (i < 96 * 96)  g_projw[i] = f2tf(proj_w[i]);
}

extern __shared__ uint32_t smu[];

__global__ void __launch_bounds__(128, 3) swin_kernel(
    const float* __restrict__ x,
    const float* __restrict__ qkv_b,
    const float* __restrict__ proj_b,
    const float* __restrict__ btab,
    float* __restrict__ out)
{
    float* sm_f = (float*)smu;
    const int tid = threadIdx.x;
    const int w   = tid >> 5;
    const int l   = tid & 31;
    const int g   = l >> 2;
    const int tg  = l & 3;
    const int win = blockIdx.x;
    const int b   = win >> 8;
    const int wq  = win & 255;
    const int wy  = wq >> 4;
    const int wx  = wq & 15;
    int* rs = (int*)&smu[RSOFF];

    // ---- Phase 0: zero padded X rows, stage bias table, region ids ----
    for (int i = tid; i < 1500; i += 128) smu[XS + 4900 + i] = 0u;   // rows 49-63
    for (int i = tid; i < 507;  i += 128) sm_f[BT + i] = btab[i];
    if (tid < NTOK) {
        int ty = tid / 7, tx = tid - 7 * ty;
        int gy = wy * 7 + ty + SHF; if (gy >= HW) gy -= HW;
        int gx = wx * 7 + tx + SHF; if (gx >= HW) gx -= HW;
        int rh = gy < 105 ? 0 : (gy < 109 ? 1 : 2);
        int rw = gx < 105 ? 0 : (gx < 109 ? 1 : 2);
        rs[tid] = 3 * rh + rw;
    }

    // gather shifted window as tf32 bits (vectorized float4)
    for (int i = tid; i < NTOK * 24; i += 128) {
        int t = i / 24, c4 = i - 24 * t;
        int ty = t / 7, tx = t - 7 * ty;
        int gy = wy * 7 + ty + SHF; if (gy >= HW) gy -= HW;
        int gx = wx * 7 + tx + SHF; if (gx >= HW) gx -= HW;
        float4 v = *(const float4*)(x + ((size_t)(b * HW + gy) * HW + gx) * 96 + c4 * 4);
        uint32_t* d = &smu[XS + t * 100 + c4 * 4];
        d[0] = f2tf(v.x); d[1] = f2tf(v.y); d[2] = f2tf(v.z); d[3] = f2tf(v.w);
    }
    __syncthreads();

    const float SCALE = 0.17677669529663687f;
    const int i0 = 16 * w + g;
    const int i1 = i0 + 8;
    // clamped row ids for bias/region lookups (padding rows read row 0's
    // table entries; their results are discarded at the prob store)
    const int ic0 = (i0 < NTOK) ? i0 : 0;
    const int ic1 = (i1 < NTOK) ? i1 : 0;

    // projection accumulators: warp owns m-tile w (rows i0,i1), all 96 cols
    float pacc[12][4];
    #pragma unroll
    for (int n = 0; n < 12; n++)
        #pragma unroll
        for (int q = 0; q < 4; q++) pacc[n][q] = 0.f;

    for (int h = 0; h < 3; ++h) {
        // ================= QKV (per-head chunk): [64,96] @ [96,96] ========
        float acc[4][3][4];
        #pragma unroll
        for (int mt = 0; mt < 4; mt++)
            #pragma unroll
            for (int jj = 0; jj < 3; jj++)
                #pragma unroll
                for (int q = 0; q < 4; q++) acc[mt][jj][q] = 0.f;

        const uint32_t* wb[3];
        #pragma unroll
        for (int jj = 0; jj < 3; jj++) {
            int jt = w * 3 + jj;
            int e  = jt >> 2;
            int d0 = (jt & 3) * 8;
            wb[jj] = g_qkvw + tg * 288 + e * 96 + h * 32 + d0 + g;
        }
        #pragma unroll
        for (int k0 = 0; k0 < 96; k0 += 8) {
            uint32_t bf[3][2];
            #pragma unroll
            for (int jj = 0; jj < 3; jj++) {
                const uint32_t* p = wb[jj] + k0 * 288;
                bf[jj][0] = p[0];
                bf[jj][1] = p[4 * 288];
            }
            #pragma unroll
            for (int mt = 0; mt < 4; mt++) {
                const uint32_t* ap = &smu[XS + (16 * mt + g) * 100 + k0 + tg];
                uint32_t a0 = ap[0], a1 = ap[800], a2 = ap[4], a3 = ap[804];
                #pragma unroll
                for (int jj = 0; jj < 3; jj++)
                    mma8(acc[mt][jj], a0, a1, a2, a3, bf[jj][0], bf[jj][1]);
            }
        }
        // epilogue: +bias, scale q, store tf32 bits to q/k/vT smem
        #pragma unroll
        for (int jj = 0; jj < 3; jj++) {
            int jt = w * 3 + jj;
            int e  = jt >> 2;
            int dl = (jt & 3) * 8 + 2 * tg;
            int gc = e * 96 + h * 32 + dl;
            float b0v = qkv_b[gc], b1v = qkv_b[gc + 1];
            #pragma unroll
            for (int mt = 0; mt < 4; mt++) {
                int r0 = 16 * mt + g, r1 = r0 + 8;
                float v00 = acc[mt][jj][0] + b0v, v01 = acc[mt][jj][1] + b1v;
                float v10 = acc[mt][jj][2] + b0v, v11 = acc[mt][jj][3] + b1v;
                if (e == 0) {
                    smu[QS + r0 * 36 + dl]     = f2tf(v00 * SCALE);
                    smu[QS + r0 * 36 + dl + 1] = f2tf(v01 * SCALE);
                    smu[QS + r1 * 36 + dl]     = f2tf(v10 * SCALE);
                    smu[QS + r1 * 36 + dl + 1] = f2tf(v11 * SCALE);
                } else if (e == 1) {
                    smu[KS + r0 * 36 + dl]     = f2tf(v00);
                    smu[KS + r0 * 36 + dl + 1] = f2tf(v01);
                    smu[KS + r1 * 36 + dl]     = f2tf(v10);
                    smu[KS + r1 * 36 + dl + 1] = f2tf(v11);
                } else {  // V transposed [d][token], stride 68
                    smu[VS + dl * 68 + r0]       = f2tf(v00);
                    smu[VS + (dl + 1) * 68 + r0] = f2tf(v01);
                    smu[VS + dl * 68 + r1]       = f2tf(v10);
                    smu[VS + (dl + 1) * 68 + r1] = f2tf(v11);
                }
            }
        }
        __syncthreads();   // (B) Q/K/V visible to all warps

        // ================= S = Q @ K^T  [64 x 56] =========================
        float sacc[7][4];
        #pragma unroll
        for (int nt = 0; nt < 7; nt++)
            #pragma unroll
            for (int q = 0; q < 4; q++) sacc[nt][q] = 0.f;
        #pragma unroll
        for (int k0 = 0; k0 < 32; k0 += 8) {
            const uint32_t* qp = &smu[QS + i0 * 36 + k0 + tg];
            uint32_t a0 = qp[0], a1 = qp[288], a2 = qp[4], a3 = qp[292];
            #pragma unroll
            for (int nt = 0; nt < 7; nt++) {
                const uint32_t* kp = &smu[KS + (nt * 8 + g) * 36 + k0 + tg];
                mma8(sacc[nt], a0, a1, a2, a3, kp[0], kp[4]);
            }
        }
        // === fused epilogue: bias+mask in regs, register softmax, prob STS ===
        {
            int yi0 = ic0 / 7, xi0 = ic0 - 7 * yi0;   // clamped: in [0,6]
            int yi1 = ic1 / 7, xi1 = ic1 - 7 * yi1;
            int ri0 = rs[ic0];
            int ri1 = rs[ic1];
            #pragma unroll
            for (int nt = 0; nt < 7; nt++) {
                #pragma unroll
                for (int q = 0; q < 2; q++) {
                    int j = nt * 8 + 2 * tg + q;
                    if (j >= NTOK) {
                        sacc[nt][q]     = -1e9f;
                        sacc[nt][q + 2] = -1e9f;
                    } else {
                        int yj = j / 7, xj = j - 7 * yj;
                        int rj = rs[j];
                        sacc[nt][q] += sm_f[BT + ((yi0 - yj + 6) * 13 + (xi0 - xj + 6)) * 3 + h]
                                       + ((ri0 != rj) ? -1e9f : 0.f);
                        sacc[nt][q + 2] += sm_f[BT + ((yi1 - yj + 6) * 13 + (xi1 - xj + 6)) * 3 + h]
                                           + ((ri1 != rj) ? -1e9f : 0.f);
                    }
                }
            }
            // row max over the 4-lane group
            float m0 = -1e30f, m1 = -1e30f;
            #pragma unroll
            for (int nt = 0; nt < 7; nt++) {
                m0 = fmaxf(m0, fmaxf(sacc[nt][0], sacc[nt][1]));
                m1 = fmaxf(m1, fmaxf(sacc[nt][2], sacc[nt][3]));
            }
            m0 = fmaxf(m0, __shfl_xor_sync(0xffffffffu, m0, 1));
            m0 = fmaxf(m0, __shfl_xor_sync(0xffffffffu, m0, 2));
            m1 = fmaxf(m1, __shfl_xor_sync(0xffffffffu, m1, 1));
            m1 = fmaxf(m1, __shfl_xor_sync(0xffffffffu, m1, 2));
            // exp + row sum
            float s0 = 0.f, s1 = 0.f;
            #pragma unroll
            for (int nt = 0; nt < 7; nt++) {
                sacc[nt][0] = __expf(sacc[nt][0] - m0);
                sacc[nt][1] = __expf(sacc[nt][1] - m0);
                sacc[nt][2] = __expf(sacc[nt][2] - m1);
                sacc[nt][3] = __expf(sacc[nt][3] - m1);
                s0 += sacc[nt][0] + sacc[nt][1];
                s1 += sacc[nt][2] + sacc[nt][3];
            }
            s0 += __shfl_xor_sync(0xffffffffu, s0, 1);
            s0 += __shfl_xor_sync(0xffffffffu, s0, 2);
            s1 += __shfl_xor_sync(0xffffffffu, s1, 1);
            s1 += __shfl_xor_sync(0xffffffffu, s1, 2);
            float inv0 = __fdividef(1.f, s0);
            float inv1 = __fdividef(1.f, s1);
            // store probs as tf32 bits
            #pragma unroll
            for (int nt = 0; nt < 7; nt++) {
                int j = nt * 8 + 2 * tg;
                smu[SMS + i0 * 60 + j]     = (i0 < NTOK) ? f2tf(sacc[nt][0] * inv0) : 0u;
                smu[SMS + i0 * 60 + j + 1] = (i0 < NTOK) ? f2tf(sacc[nt][1] * inv0) : 0u;
                smu[SMS + i1 * 60 + j]     = (i1 < NTOK) ? f2tf(sacc[nt][2] * inv1) : 0u;
                smu[SMS + i1 * 60 + j + 1] = (i1 < NTOK) ? f2tf(sacc[nt][3] * inv1) : 0u;
            }
        }
        __syncthreads();   // probs visible

        // ================= O_h = P @ V  [64 x 32] =========================
        float oacc[4][4];
        #pragma unroll
        for (int nt = 0; nt < 4; nt++)
            #pragma unroll
            for (int q = 0; q < 4; q++) oacc[nt][q] = 0.f;
        #pragma unroll
        for (int k0 = 0; k0 < 56; k0 += 8) {
            const uint32_t* pp = &smu[SMS + i0 * 60 + k0 + tg];
            uint32_t a0 = pp[0], a1 = pp[480], a2 = pp[4], a3 = pp[484];
            #pragma unroll
            for (int nt = 0; nt < 4; nt++) {
                const uint32_t* vp = &smu[VS + (nt * 8 + g) * 68 + k0 + tg];
                mma8(oacc[nt], a0, a1, a2, a3, vp[0], vp[4]);
            }
        }
        __syncthreads();   // (C) all PV reads done before OH clobbers SMS rows

        #pragma unroll
        for (int nt = 0; nt < 4; nt++) {
            int c = nt * 8 + 2 * tg;
            smu[OH + i0 * 36 + c]     = f2tf(oacc[nt][0]);
            smu[OH + i0 * 36 + c + 1] = f2tf(oacc[nt][1]);
            smu[OH + i1 * 36 + c]     = f2tf(oacc[nt][2]);
            smu[OH + i1 * 36 + c + 1] = f2tf(oacc[nt][3]);
        }
        __syncthreads();   // OH visible

        // === proj partial (own m-tile): pacc += O_h[i0/i1,:] @ proj_w =====
        #pragma unroll
        for (int k0 = 0; k0 < 32; k0 += 8) {
            const uint32_t* ap = &smu[OH + i0 * 36 + k0 + tg];
            uint32_t a0 = ap[0], a1 = ap[288], a2 = ap[4], a3 = ap[292];
            const uint32_t* bp = g_projw + (h * 32 + k0 + tg) * 96 + g;
            #pragma unroll
            for (int n = 0; n < 12; n++)
                mma8(pacc[n], a0, a1, a2, a3, bp[n * 8], bp[n * 8 + 4 * 96]);
        }
        // no barrier: next head's conflicting writes are behind sync (B)/(C)
    }  // heads

    // ================= +proj_b, scatter to rolled-back gmem ==============
    #pragma unroll
    for (int half = 0; half < 2; half++) {
        int r = half ? i1 : i0;
        if (r < NTOK) {
            int ty = r / 7, tx = r - 7 * ty;
            int gy = wy * 7 + ty + SHF; if (gy >= HW) gy -= HW;
            int gx = wx * 7 + tx + SHF; if (gx >= HW) gx -= HW;
            float* op = out + ((size_t)(b * HW + gy) * HW + gx) * 96;
            #pragma unroll
            for (int n = 0; n < 12; n++) {
                int c = n * 8 + 2 * tg;
                float2 v;
                v.x = pacc[n][2 * half]     + proj_b[c];
                v.y = pacc[n][2 * half + 1] + proj_b[c + 1];
                *(float2*)(op + c) = v;
            }
        }
    }
}

extern "C" void kernel_launch(void* const* d_in, const int* in_sizes, int n_in,
                              void* d_out, int out_size)
{
    const float* x      = (const float*)d_in[0];
    const float* qkv_w  = (const float*)d_in[1];
    const float* qkv_b  = (const float*)d_in[2];
    const float* proj_w = (const float*)d_in[3];
    const float* proj_b = (const float*)d_in[4];
    const float* btab   = (const float*)d_in[5];
    float* out = (float*)d_out;

    cudaFuncSetAttribute(swin_kernel,
                         cudaFuncAttributeMaxDynamicSharedMemorySize,
                         SMEM_BYTES);

    prep_kernel<<<108, 256>>>(qkv_w, proj_w);

    const int n_windows = BATCH * NWIN * NWIN;  // 8192
    swin_kernel<<<n_windows, 128, SMEM_BYTES>>>(
        x, qkv_b, proj_b, btab, out);
}

// round 14
// speedup vs baseline: 1.9876x; 1.9876x over previous
#include <cuda_runtime.h>
#include <cstdint>

#define WSZ   7
#define SHF   3
#define NTOK  49
#define HW    112
#define NWIN  16
#define BATCH 32

// shared memory layout (32-bit word offsets). Matrix tiles hold tf32 BIT
// PATTERNS (uint32); BT holds floats.
#define XS    0        // 64 x 100 (x window, tf32 bits, rows 49-63 zero)
#define QS    6400     // 64 x 36   tf32 bits
#define KS    8704     // 64 x 36   tf32 bits
#define VS    11008    // V^T 32 x 68 tf32 bits
#define SMS   13312    // 64 x 60  probs (tf32 bits)
#define OH    13312    // 64 x 36  per-head attn out (tf32 bits), aliases SMS
#define BT    17152    // 507 bias table (float)
#define RSOFF 17664    // 64 ints (region ids)
#define SMEM_WORDS (17664 + 64)
#define SMEM_BYTES (SMEM_WORDS * 4)

// Weights in FRAGMENT order: [ntile][ks2][lane][4], lane=(g<<2)|tg.
// The 4 words are {b0(ks=2*ks2), b1(ks=2*ks2), b0(ks=2*ks2+1), b1(ks=2*ks2+1)}
// where b0 = W[(ks*8+tg)*C + ntile*8+g], b1 = W[(ks*8+tg+4)*C + ntile*8+g].
__device__ uint32_t g_qkvw[36 * 6 * 32 * 4];   // 27648: qkv_w [96][288]
__device__ uint32_t g_projw[12 * 6 * 32 * 4];  // 9216:  proj_w [96][96]

__device__ __forceinline__ uint32_t f2tf(float f) {
    uint32_t r;
    asm("cvt.rna.tf32.f32 %0, %1;" : "=r"(r) : "f"(f));
    return r;
}

__device__ __forceinline__ void mma8(float* c,
    uint32_t a0, uint32_t a1, uint32_t a2, uint32_t a3,
    uint32_t b0, uint32_t b1)
{
    asm volatile(
        "mma.sync.aligned.m16n8k8.row.col.f32.tf32.tf32.f32 "
        "{%0,%1,%2,%3},{%4,%5,%6,%7},{%8,%9},{%0,%1,%2,%3};\n"
        : "+f"(c[0]), "+f"(c[1]), "+f"(c[2]), "+f"(c[3])
        : "r"(a0), "r"(a1), "r"(a2), "r"(a3), "r"(b0), "r"(b1));
}

__global__ void __launch_bounds__(256) prep_kernel(
    const float* __restrict__ qkv_w, const float* __restrict__ proj_w)
{
    int i = blockIdx.x * 256 + threadIdx.x;
    if (i < 36 * 6 * 32 * 4) {            // qkv fragments
        int c   = i & 3;
        int l   = (i >> 2) & 31;
        int ks2 = (i >> 7) % 6;
        int nt  = i / 768;
        int g = l >> 2, tg = l & 3;
        int ks   = 2 * ks2 + (c >> 1);
        int brow = ks * 8 + tg + ((c & 1) ? 4 : 0);
        g_qkvw[i] = f2tf(qkv_w[brow * 288 + nt * 8 + g]);
    }
    if (i < 12 * 6 * 32 * 4) {            // proj fragments
        int c   = i & 3;
        int l   = (i >> 2) & 31;
        int ks2 = (i >> 7) % 6;
        int nt  = i / 768;
        int g = l >> 2, tg = l & 3;
        int ks   = 2 * ks2 + (c >> 1);
        int brow = ks * 8 + tg + ((c & 1) ? 4 : 0);
        g_projw[i] = f2tf(proj_w[brow * 96 + nt * 8 + g]);
    }
}

extern __shared__ uint32_t smu[];

__global__ void __launch_bounds__(128, 3) swin_kernel(
    const float* __restrict__ x,
    const float* __restrict__ qkv_b,
    const float* __restrict__ proj_b,
    const float* __restrict__ btab,
    float* __restrict__ out)
{
    float* sm_f = (float*)smu;
    const int tid = threadIdx.x;
    const int w   = tid >> 5;
    const int l   = tid & 31;
    const int g   = l >> 2;
    const int tg  = l & 3;
    const int win = blockIdx.x;
    const int b   = win >> 8;
    const int wq  = win & 255;
    const int wy  = wq >> 4;
    const int wx  = wq & 15;
    int* rs = (int*)&smu[RSOFF];

    // ---- Phase 0: zero padded X rows, stage bias table, region ids ----
    for (int i = tid; i < 1500; i += 128) smu[XS + 4900 + i] = 0u;   // rows 49-63
    for (int i = tid; i < 507;  i += 128) sm_f[BT + i] = btab[i];
    if (tid < NTOK) {
        int ty = tid / 7, tx = tid - 7 * ty;
        int gy = wy * 7 + ty + SHF; if (gy >= HW) gy -= HW;
        int gx = wx * 7 + tx + SHF; if (gx >= HW) gx -= HW;
        int rh = gy < 105 ? 0 : (gy < 109 ? 1 : 2);
        int rw = gx < 105 ? 0 : (gx < 109 ? 1 : 2);
        rs[tid] = 3 * rh + rw;
    }

    // gather shifted window as tf32 bits (vectorized float4)
    for (int i = tid; i < NTOK * 24; i += 128) {
        int t = i / 24, c4 = i - 24 * t;
        int ty = t / 7, tx = t - 7 * ty;
        int gy = wy * 7 + ty + SHF; if (gy >= HW) gy -= HW;
        int gx = wx * 7 + tx + SHF; if (gx >= HW) gx -= HW;
        float4 v = *(const float4*)(x + ((size_t)(b * HW + gy) * HW + gx) * 96 + c4 * 4);
        uint32_t* d = &smu[XS + t * 100 + c4 * 4];
        d[0] = f2tf(v.x); d[1] = f2tf(v.y); d[2] = f2tf(v.z); d[3] = f2tf(v.w);
    }
    __syncthreads();

    const float SCALE = 0.17677669529663687f;
    const int i0 = 16 * w + g;
    const int i1 = i0 + 8;
    const int ic0 = (i0 < NTOK) ? i0 : 0;   // clamped row ids for bias/region
    const int ic1 = (i1 < NTOK) ? i1 : 0;

    // projection accumulators: warp owns m-tile w (rows i0,i1), all 96 cols
    float pacc[12][4];
    #pragma unroll
    for (int n = 0; n < 12; n++)
        #pragma unroll
        for (int q = 0; q < 4; q++) pacc[n][q] = 0.f;

    for (int h = 0; h < 3; ++h) {
        // ================= QKV (per-head chunk): [64,96] @ [96,96] ========
        float acc[4][3][4];
        #pragma unroll
        for (int mt = 0; mt < 4; mt++)
            #pragma unroll
            for (int jj = 0; jj < 3; jj++)
                #pragma unroll
                for (int q = 0; q < 4; q++) acc[mt][jj][q] = 0.f;

        // fragment-order base pointers: ntile_global = e*12 + h*4 + (jt&3)
        const uint4* wb[3];
        #pragma unroll
        for (int jj = 0; jj < 3; jj++) {
            int jt  = w * 3 + jj;
            int ntg = (jt >> 2) * 12 + h * 4 + (jt & 3);
            wb[jj] = (const uint4*)&g_qkvw[(ntg * 6 * 32 + l) * 4];
        }
        #pragma unroll
        for (int ks2 = 0; ks2 < 6; ks2++) {
            uint4 bf[3];
            #pragma unroll
            for (int jj = 0; jj < 3; jj++) bf[jj] = wb[jj][ks2 * 32];
            #pragma unroll
            for (int mt = 0; mt < 4; mt++) {
                const uint32_t* ap = &smu[XS + (16 * mt + g) * 100 + ks2 * 16 + tg];
                uint32_t a0 = ap[0], a1 = ap[800], a2 = ap[4],  a3 = ap[804];
                uint32_t c0 = ap[8], c1 = ap[808], c2 = ap[12], c3 = ap[812];
                #pragma unroll
                for (int jj = 0; jj < 3; jj++) {
                    mma8(acc[mt][jj], a0, a1, a2, a3, bf[jj].x, bf[jj].y);
                    mma8(acc[mt][jj], c0, c1, c2, c3, bf[jj].z, bf[jj].w);
                }
            }
        }
        // epilogue: +bias, scale q, store tf32 bits to q/k/vT smem
        #pragma unroll
        for (int jj = 0; jj < 3; jj++) {
            int jt = w * 3 + jj;
            int e  = jt >> 2;
            int dl = (jt & 3) * 8 + 2 * tg;
            int gc = e * 96 + h * 32 + dl;
            float b0v = qkv_b[gc], b1v = qkv_b[gc + 1];
            #pragma unroll
            for (int mt = 0; mt < 4; mt++) {
                int r0 = 16 * mt + g, r1 = r0 + 8;
                float v00 = acc[mt][jj][0] + b0v, v01 = acc[mt][jj][1] + b1v;
                float v10 = acc[mt][jj][2] + b0v, v11 = acc[mt][jj][3] + b1v;
                if (e == 0) {
                    smu[QS + r0 * 36 + dl]     = f2tf(v00 * SCALE);
                    smu[QS + r0 * 36 + dl + 1] = f2tf(v01 * SCALE);
                    smu[QS + r1 * 36 + dl]     = f2tf(v10 * SCALE);
                    smu[QS + r1 * 36 + dl + 1] = f2tf(v11 * SCALE);
                } else if (e == 1) {
                    smu[KS + r0 * 36 + dl]     = f2tf(v00);
                    smu[KS + r0 * 36 + dl + 1] = f2tf(v01);
                    smu[KS + r1 * 36 + dl]     = f2tf(v10);
                    smu[KS + r1 * 36 + dl + 1] = f2tf(v11);
                } else {  // V transposed [d][token], stride 68
                    smu[VS + dl * 68 + r0]       = f2tf(v00);
                    smu[VS + (dl + 1) * 68 + r0] = f2tf(v01);
                    smu[VS + dl * 68 + r1]       = f2tf(v10);
                    smu[VS + (dl + 1) * 68 + r1] = f2tf(v11);
                }
            }
        }
        __syncthreads();   // (B) Q/K/V visible to all warps

        // ================= S = Q @ K^T  [64 x 56] =========================
        float sacc[7][4];
        #pragma unroll
        for (int nt = 0; nt < 7; nt++)
            #pragma unroll
            for (int q = 0; q < 4; q++) sacc[nt][q] = 0.f;
        #pragma unroll
        for (int k0 = 0; k0 < 32; k0 += 8) {
            const uint32_t* qp = &smu[QS + i0 * 36 + k0 + tg];
            uint32_t a0 = qp[0], a1 = qp[288], a2 = qp[4], a3 = qp[292];
            #pragma unroll
            for (int nt = 0; nt < 7; nt++) {
                const uint32_t* kp = &smu[KS + (nt * 8 + g) * 36 + k0 + tg];
                mma8(sacc[nt], a0, a1, a2, a3, kp[0], kp[4]);
            }
        }
        // === fused epilogue: bias+mask in regs, register softmax, prob STS ===
        {
            int yi0 = ic0 / 7, xi0 = ic0 - 7 * yi0;
            int yi1 = ic1 / 7, xi1 = ic1 - 7 * yi1;
            int ri0 = rs[ic0];
            int ri1 = rs[ic1];
            #pragma unroll
            for (int nt = 0; nt < 7; nt++) {
                #pragma unroll
                for (int q = 0; q < 2; q++) {
                    int j = nt * 8 + 2 * tg + q;
                    if (j >= NTOK) {
                        sacc[nt][q]     = -1e9f;
                        sacc[nt][q + 2] = -1e9f;
                    } else {
                        int yj = j / 7, xj = j - 7 * yj;
                        int rj = rs[j];
                        sacc[nt][q] += sm_f[BT + ((yi0 - yj + 6) * 13 + (xi0 - xj + 6)) * 3 + h]
                                       + ((ri0 != rj) ? -1e9f : 0.f);
                        sacc[nt][q + 2] += sm_f[BT + ((yi1 - yj + 6) * 13 + (xi1 - xj + 6)) * 3 + h]
                                           + ((ri1 != rj) ? -1e9f : 0.f);
                    }
                }
            }
            float m0 = -1e30f, m1 = -1e30f;
            #pragma unroll
            for (int nt = 0; nt < 7; nt++) {
                m0 = fmaxf(m0, fmaxf(sacc[nt][0], sacc[nt][1]));
                m1 = fmaxf(m1, fmaxf(sacc[nt][2], sacc[nt][3]));
            }
            m0 = fmaxf(m0, __shfl_xor_sync(0xffffffffu, m0, 1));
            m0 = fmaxf(m0, __shfl_xor_sync(0xffffffffu, m0, 2));
            m1 = fmaxf(m1, __shfl_xor_sync(0xffffffffu, m1, 1));
            m1 = fmaxf(m1, __shfl_xor_sync(0xffffffffu, m1, 2));
            float s0 = 0.f, s1 = 0.f;
            #pragma unroll
            for (int nt = 0; nt < 7; nt++) {
                sacc[nt][0] = __expf(sacc[nt][0] - m0);
                sacc[nt][1] = __expf(sacc[nt][1] - m0);
                sacc[nt][2] = __expf(sacc[nt][2] - m1);
                sacc[nt][3] = __expf(sacc[nt][3] - m1);
                s0 += sacc[nt][0] + sacc[nt][1];
                s1 += sacc[nt][2] + sacc[nt][3];
            }
            s0 += __shfl_xor_sync(0xffffffffu, s0, 1);
            s0 += __shfl_xor_sync(0xffffffffu, s0, 2);
            s1 += __shfl_xor_sync(0xffffffffu, s1, 1);
            s1 += __shfl_xor_sync(0xffffffffu, s1, 2);
            float inv0 = __fdividef(1.f, s0);
            float inv1 = __fdividef(1.f, s1);
            #pragma unroll
            for (int nt = 0; nt < 7; nt++) {
                int j = nt * 8 + 2 * tg;
                smu[SMS + i0 * 60 + j]     = (i0 < NTOK) ? f2tf(sacc[nt][0] * inv0) : 0u;
                smu[SMS + i0 * 60 + j + 1] = (i0 < NTOK) ? f2tf(sacc[nt][1] * inv0) : 0u;
                smu[SMS + i1 * 60 + j]     = (i1 < NTOK) ? f2tf(sacc[nt][2] * inv1) : 0u;
                smu[SMS + i1 * 60 + j + 1] = (i1 < NTOK) ? f2tf(sacc[nt][3] * inv1) : 0u;
            }
        }
        __syncthreads();   // probs visible

        // ================= O_h = P @ V  [64 x 32] =========================
        float oacc[4][4];
        #pragma unroll
        for (int nt = 0; nt < 4; nt++)
            #pragma unroll
            for (int q = 0; q < 4; q++) oacc[nt][q] = 0.f;
        #pragma unroll
        for (int k0 = 0; k0 < 56; k0 += 8) {
            const uint32_t* pp = &smu[SMS + i0 * 60 + k0 + tg];
            uint32_t a0 = pp[0], a1 = pp[480], a2 = pp[4], a3 = pp[484];
            #pragma unroll
            for (int nt = 0; nt < 4; nt++) {
                const uint32_t* vp = &smu[VS + (nt * 8 + g) * 68 + k0 + tg];
                mma8(oacc[nt], a0, a1, a2, a3, vp[0], vp[4]);
            }
        }
        __syncthreads();   // (C) all PV reads done before OH clobbers SMS rows

        #pragma unroll
        for (int nt = 0; nt < 4; nt++) {
            int c = nt * 8 + 2 * tg;
            smu[OH + i0 * 36 + c]     = f2tf(oacc[nt][0]);
            smu[OH + i0 * 36 + c + 1] = f2tf(oacc[nt][1]);
            smu[OH + i1 * 36 + c]     = f2tf(oacc[nt][2]);
            smu[OH + i1 * 36 + c + 1] = f2tf(oacc[nt][3]);
        }
        __syncthreads();   // OH visible

        // === proj partial (own m-tile): pacc += O_h[i0/i1,:] @ proj_w =====
        #pragma unroll
        for (int s = 0; s < 2; s++) {
            int ks2 = h * 2 + s;
            const uint32_t* ap = &smu[OH + i0 * 36 + s * 16 + tg];
            uint32_t a0 = ap[0], a1 = ap[288], a2 = ap[4],  a3 = ap[292];
            uint32_t c0 = ap[8], c1 = ap[296], c2 = ap[12], c3 = ap[300];
            const uint4* pw = (const uint4*)&g_projw[(ks2 * 32 + l) * 4];
            #pragma unroll
            for (int n = 0; n < 12; n++) {
                uint4 bf = pw[n * 6 * 32];
                mma8(pacc[n], a0, a1, a2, a3, bf.x, bf.y);
                mma8(pacc[n], c0, c1, c2, c3, bf.z, bf.w);
            }
        }
        // no barrier: next head's conflicting writes are behind sync (B)/(C)
    }  // heads

    // ================= +proj_b, scatter to rolled-back gmem ==============
    #pragma unroll
    for (int half = 0; half < 2; half++) {
        int r = half ? i1 : i0;
        if (r < NTOK) {
            int ty = r / 7, tx = r - 7 * ty;
            int gy = wy * 7 + ty + SHF; if (gy >= HW) gy -= HW;
            int gx = wx * 7 + tx + SHF; if (gx >= HW) gx -= HW;
            float* op = out + ((size_t)(b * HW + gy) * HW + gx) * 96;
            #pragma unroll
            for (int n = 0; n < 12; n++) {
                int c = n * 8 + 2 * tg;
                float2 v;
                v.x = pacc[n][2 * half]     + proj_b[c];
                v.y = pacc[n][2 * half + 1] + proj_b[c + 1];
                *(float2*)(op + c) = v;
            }
        }
    }
}

extern "C" void kernel_launch(void* const* d_in, const int* in_sizes, int n_in,
                              void* d_out, int out_size)
{
    const float* x      = (const float*)d_in[0];
    const float* qkv_w  = (const float*)d_in[1];
    const float* qkv_b  = (const float*)d_in[2];
    const float* proj_w = (const float*)d_in[3];
    const float* proj_b = (const float*)d_in[4];
    const float* btab   = (const float*)d_in[5];
    float* out = (float*)d_out;

    cudaFuncSetAttribute(swin_kernel,
                         cudaFuncAttributeMaxDynamicSharedMemorySize,
                         SMEM_BYTES);

    prep_kernel<<<108, 256>>>(qkv_w, proj_w);

    const int n_windows = BATCH * NWIN * NWIN;  // 8192
    swin_kernel<<<n_windows, 128, SMEM_BYTES>>>(
        x, qkv_b, proj_b, btab, out);
}